// round 5
// baseline (speedup 1.0000x reference)
#include <cuda_runtime.h>
#include <cuda_bf16.h>

#define KB    64      // boxes
#define GRID  128     // block b handles striped rows {b, b+128, b+256, b+384}
#define TPB   1024    // 2 pixels per thread (float2)

__device__ float2       g_part[GRID];
__device__ unsigned int g_cnt;   // zero at load; wraps back to 0 every run (deterministic)

__device__ __forceinline__ float sqrt_approx(float x) {
    float r; asm("sqrt.approx.f32 %0, %1;" : "=f"(r) : "f"(x)); return r;
}

__global__ __launch_bounds__(TPB) void lz_fused_kernel(
    const float* __restrict__ cm,      // center_maps (batch 0 = first 262144)
    const float* __restrict__ smap,    // scale_maps (batch 0)
    const float* __restrict__ ann,     // annotations (batch 0 = 64 float4)
    const void*  __restrict__ stridep, // stride scalar (int32 or float32)
    float* __restrict__ out)
{
    __shared__ float4 Lg[4][KB];      // per-row box record {fx1, fx2, A, C}
    __shared__ float  Ldy2[4][KB];    // per-row precomputed dy^2
    __shared__ float  Scol[4][KB];    // per-row scatter column
    __shared__ int    Sj[4][KB];      // flattened scatter index
    __shared__ float  Slh[4][KB];     // log(height)
    __shared__ int    cg[4][2], cs[4][2], ng[4], ns[4];
    __shared__ float  r_c[32], r_s[32];
    __shared__ int    s_last;

    const int tid = threadIdx.x;
    const int b   = blockIdx.x;

    // ---- hoisted map load: overlap DRAM latency with the whole preamble ----
    const int rmain = tid >> 8;          // which of the 4 striped rows
    const int cgrp  = tid & 255;         // float2 column group
    const int y     = b + (rmain << 7);  // striped row
    const int gq    = y * 256 + cgrp;    // float2 index into maps
    const float2 cm2 = ((const float2*)cm)[gq];

    // ---- phase A: 256 threads = (4 rows) x (64 boxes): predicates + ballots ----
    int rr = 0, k = 0;
    int x1 = 0, y1 = 0, x2 = 0, y2 = 0, cx = 0, cy = 0;
    float A = 0.f, B = 0.f, C = 0.f, LH = 0.f;
    bool pg = false, ps = false;
    unsigned mg = 0, ms = 0;
    if (tid < 256) {
        rr = tid >> 6;  k = tid & 63;
        const int yr = b + (rr << 7);
        float stridef = 4.0f;
        if (stridep) {
            int iv = ((const int*)stridep)[0];
            stridef = (iv > 0 && iv <= 65536) ? (float)iv : __int_as_float(iv);
        }
        const float inv = 1.0f / stridef;
        const float4 ab = ((const float4*)ann)[k];
        x1 = (int)floorf(ab.x * inv);  y1 = (int)floorf(ab.y * inv);
        x2 = (int)floorf(ab.z * inv);  y2 = (int)floorf(ab.w * inv);
        cx = (x1 + x2) >> 1;  cy = (y1 + y2) >> 1;
        A = (float)(x1 + cx);  B = (float)(y1 + cy);
        C = -0.5f / sqrtf((float)cx*(float)cx + (float)cy*(float)cy);
        LH = __logf((float)(y2 - y1));
        pg = (yr >= y1) && (yr < y2);                 // this row intersects box
        ps = ((unsigned)(yr - cy + 2)) <= 4u;         // scatter diagonal hits row
        mg = __ballot_sync(0xffffffffu, pg);
        ms = __ballot_sync(0xffffffffu, ps);
        if ((k & 31) == 0) { cg[rr][k>>5] = __popc(mg); cs[rr][k>>5] = __popc(ms); }
    }
    __syncthreads();
    // ---- phase B: deterministic order-preserving per-row compaction ----
    if (tid < 256) {
        const unsigned lt = (1u << (k & 31)) - 1u;
        const int h  = k >> 5;
        const int og = (h ? cg[rr][0] : 0) + __popc(mg & lt);
        const int os = (h ? cs[rr][0] : 0) + __popc(ms & lt);
        const int yr = b + (rr << 7);
        if (pg) {
            Lg[rr][og] = make_float4((float)x1, (float)x2, A, C);
            const float dy = (float)yr - B;
            Ldy2[rr][og] = dy * dy;
        }
        if (ps) {
            const int dyo = yr - cy;
            Scol[rr][os] = (float)(cx + dyo);
            Sj[rr][os]   = (dyo + 2) * KB + k;   // last-write-wins order
            Slh[rr][os]  = LH;
        }
        if (k == 0) { ng[rr] = cg[rr][0] + cg[rr][1]; ns[rr] = cs[rr][0] + cs[rr][1]; }
    }
    __syncthreads();

    // ---- main pass: each thread = 2 consecutive x pixels of its striped row ----
    const int   x0  = cgrp << 1;
    const float fx0 = (float)x0;

    float gmax[2] = {0.f,0.f};
    float blog[2] = {0.f,0.f};
    int   maxj[2] = {-1,-1};
    int   posm = 0, cenm = 0;

    const int NG = ng[rmain], NS = ns[rmain];
    for (int kk = 0; kk < NG; kk++) {
        const float4 bd = Lg[rmain][kk];          // {fx1, fx2, A, C}
        if (fx0 + 1.0f >= bd.x && fx0 < bd.y) {
            const float dy2 = Ldy2[rmain][kk];
            #pragma unroll
            for (int i = 0; i < 2; i++) {
                const float fx = fx0 + (float)i;
                if (fx >= bd.x && fx < bd.y) {
                    posm |= (1 << i);
                    const float dx = fx - bd.z;
                    const float d  = sqrt_approx(fmaf(dx, dx, dy2));
                    gmax[i] = fmaxf(gmax[i], __expf(bd.w * d));
                }
            }
        }
    }
    for (int kk = 0; kk < NS; kk++) {
        const int t = (int)Scol[rmain][kk] - x0;
        if ((unsigned)t <= 1u) {
            const int j = Sj[rmain][kk];
            if (j > maxj[t]) { maxj[t] = j; blog[t] = Slh[rmain][kk]; }
            if (j >= 2*KB && j < 3*KB) cenm |= (1 << t);   // dyo == 0 band
        }
    }

    // ---- per-pixel loss terms ----
    const float pv[2] = {cm2.x, cm2.y};
    float csum = 0.f, ssum = 0.f;
    #pragma unroll
    for (int i = 0; i < 2; i++) {
        const float p = fminf(fmaxf(pv[i], 1e-4f), 0.9999f);
        if (cenm & (1 << i)) {
            const float q = 1.0f - p;
            csum += q * q * (-__logf(p));                    // ALPHA=1, GAMMA=2
        } else if (posm & (1 << i)) {
            float q = 1.0f - gmax[i];
            float w = q * q; w = w * w;                      // BETA=4
            csum += w * p * p * (-__logf(1.0f - p));
        }
        if (maxj[i] >= 0) {
            const float d = fabsf(blog[i] - smap[(size_t)gq * 2 + i]);
            ssum += (d <= 1.0f) ? 0.5f * d * d : (d - 0.5f);
        }
    }

    // ---- block reduce (32 warps) ----
    #pragma unroll
    for (int off = 16; off; off >>= 1) {
        csum += __shfl_down_sync(0xffffffffu, csum, off);
        ssum += __shfl_down_sync(0xffffffffu, ssum, off);
    }
    if ((tid & 31) == 0) { r_c[tid>>5] = csum; r_s[tid>>5] = ssum; }
    __syncthreads();
    if (tid < 32) {
        csum = r_c[tid]; ssum = r_s[tid];
        #pragma unroll
        for (int off = 16; off; off >>= 1) {
            csum += __shfl_down_sync(0xffffffffu, csum, off);
            ssum += __shfl_down_sync(0xffffffffu, ssum, off);
        }
    }
    if (tid == 0) {
        g_part[b] = make_float2(csum, ssum);
        __threadfence();
        unsigned old = atomicInc(&g_cnt, GRID - 1);   // wraps to 0 -> self-resetting
        s_last = (old == GRID - 1);
    }
    __syncthreads();

    // ---- last block finalizes (128 partials) ----
    if (s_last) {
        float c2 = 0.f, s2 = 0.f;
        if (tid < GRID) {
            volatile float* vp = (volatile float*)g_part;
            c2 = vp[tid * 2];
            s2 = vp[tid * 2 + 1];
        }
        #pragma unroll
        for (int off = 16; off; off >>= 1) {
            c2 += __shfl_down_sync(0xffffffffu, c2, off);
            s2 += __shfl_down_sync(0xffffffffu, s2, off);
        }
        if ((tid & 31) == 0 && tid < GRID) { r_c[tid>>5] = c2; r_s[tid>>5] = s2; }
        __syncthreads();
        if (tid < 4) {
            c2 = r_c[tid]; s2 = r_s[tid];
            #pragma unroll
            for (int off = 2; off; off >>= 1) {
                c2 += __shfl_down_sync(0x0000000fu, c2, off);
                s2 += __shfl_down_sync(0x0000000fu, s2, off);
            }
            if (tid == 0) {
                out[0] = c2 * (1.0f / 64.0f);
                out[1] = s2 * (1.0f / 64.0f);
            }
        }
    }
}

extern "C" void kernel_launch(void* const* d_in, const int* in_sizes, int n_in,
                              void* d_out, int out_size) {
    const float* cm   = (const float*)d_in[0];
    const float* sm   = (const float*)d_in[1];
    const float* ann  = (const float*)d_in[2];
    const void*  strp = (n_in > 3) ? d_in[3] : nullptr;
    float* out = (float*)d_out;

    lz_fused_kernel<<<GRID, TPB>>>(cm, sm, ann, strp, out);
}

// round 6
// speedup vs baseline: 1.0239x; 1.0239x over previous
#include <cuda_runtime.h>
#include <cuda_bf16.h>

#define KB    64      // boxes
#define GRID  128     // block b handles striped rows {b, b+128, b+256, b+384}
#define TPB   1024    // 2 pixels per thread (float2)

__device__ float2       g_part[GRID];
__device__ unsigned int g_cnt;   // zero at load; wraps back to 0 every run (deterministic)

__device__ __forceinline__ float sqrt_approx(float x) {
    float r; asm("sqrt.approx.f32 %0, %1;" : "=f"(r) : "f"(x)); return r;
}

__global__ __launch_bounds__(TPB) void lz_fused_kernel(
    const float* __restrict__ cm,      // center_maps (batch 0 = first 262144)
    const float* __restrict__ smap,    // scale_maps (batch 0)
    const float* __restrict__ ann,     // annotations (batch 0 = 64 float4)
    const void*  __restrict__ stridep, // stride scalar (int32 or float32)
    float* __restrict__ out)
{
    __shared__ float4 Lg[4][KB];      // per-row box record {fx1, fx2, A, C}
    __shared__ float  Ldy2[4][KB];    // per-row precomputed dy^2
    __shared__ float  Scol[4][KB];    // per-row scatter column
    __shared__ int    Sj[4][KB];      // flattened scatter index
    __shared__ float  Slh[4][KB];     // log(height)
    __shared__ int    ng[4], ns[4];
    __shared__ float  r_c[32], r_s[32];
    __shared__ int    s_last;

    const int tid  = threadIdx.x;
    const int b    = blockIdx.x;
    const int lane = tid & 31;

    // ---- hoisted map load: overlap DRAM latency with the whole preamble ----
    const int rmain = tid >> 8;          // which of the 4 striped rows
    const int cgrp  = tid & 255;         // float2 column group
    const int y     = b + (rmain << 7);  // striped row
    const int gq    = y * 256 + cgrp;    // float2 index into maps
    const float2 cm2 = ((const float2*)cm)[gq];

    // ---- phase A: warps 0..3, one warp per row; lane handles boxes {lane, lane+32}.
    //      In-warp ballot prefix -> compacted per-row lists. No cross-warp exchange.
    if (tid < 128) {
        const int rr = tid >> 5;
        const int yr = b + (rr << 7);
        float stridef = 4.0f;
        if (stridep) {
            int iv = ((const int*)stridep)[0];
            stridef = (iv > 0 && iv <= 65536) ? (float)iv : __int_as_float(iv);
        }
        const float inv = 1.0f / stridef;
        const unsigned lt = (1u << lane) - 1u;

        int   ngacc = 0, nsacc = 0;
        #pragma unroll
        for (int half = 0; half < 2; half++) {
            const int k = lane + half * 32;
            const float4 ab = ((const float4*)ann)[k];
            const int x1 = (int)floorf(ab.x * inv);
            const int y1 = (int)floorf(ab.y * inv);
            const int x2 = (int)floorf(ab.z * inv);
            const int y2 = (int)floorf(ab.w * inv);
            const int cx = (x1 + x2) >> 1, cy = (y1 + y2) >> 1;
            const float A = (float)(x1 + cx);
            const float B = (float)(y1 + cy);
            const float C = -0.5f / sqrtf((float)cx*(float)cx + (float)cy*(float)cy);
            const bool pg = (yr >= y1) && (yr < y2);
            const bool ps = ((unsigned)(yr - cy + 2)) <= 4u;
            const unsigned mg = __ballot_sync(0xffffffffu, pg);
            const unsigned ms = __ballot_sync(0xffffffffu, ps);
            if (pg) {
                const int og = ngacc + __popc(mg & lt);
                Lg[rr][og] = make_float4((float)x1, (float)x2, A, C);
                const float dy = (float)yr - B;
                Ldy2[rr][og] = dy * dy;
            }
            if (ps) {
                const int os  = nsacc + __popc(ms & lt);
                const int dyo = yr - cy;
                Scol[rr][os] = (float)(cx + dyo);
                Sj[rr][os]   = (dyo + 2) * KB + k;   // last-write-wins order
                Slh[rr][os]  = __logf((float)(y2 - y1));
            }
            ngacc += __popc(mg);
            nsacc += __popc(ms);
        }
        if (lane == 0) { ng[rr] = ngacc; ns[rr] = nsacc; }
    }
    __syncthreads();

    // ---- main pass: warp-level box filter, then 2 px/thread ----
    const int   x0   = cgrp << 1;
    const float fx0  = (float)x0;
    const int   wx0  = (cgrp & ~31) << 1;          // warp's first pixel x
    const float fwx0 = (float)wx0;
    const float fwxe = (float)(wx0 + 63);          // warp's last pixel x

    float gmax[2] = {0.f,0.f};
    float blog[2] = {0.f,0.f};
    int   maxj[2] = {-1,-1};
    int   posm = 0, cenm = 0;

    const int NG = ng[rmain], NS = ns[rmain];
    for (int base = 0; base < NG; base += 32) {
        const int idx = base + lane;
        bool ov = false;
        if (idx < NG) {
            const float4 bd = Lg[rmain][idx];
            ov = (fwxe >= bd.x) && (fwx0 < bd.y);
        }
        unsigned m = __ballot_sync(0xffffffffu, ov);
        while (m) {
            const int kk = base + (__ffs(m) - 1); m &= m - 1;
            const float4 bd  = Lg[rmain][kk];      // broadcast LDS
            const float  dy2 = Ldy2[rmain][kk];
            #pragma unroll
            for (int i = 0; i < 2; i++) {
                const float fx = fx0 + (float)i;
                if (fx >= bd.x && fx < bd.y) {
                    posm |= (1 << i);
                    const float dx = fx - bd.z;
                    const float d  = sqrt_approx(fmaf(dx, dx, dy2));
                    gmax[i] = fmaxf(gmax[i], __expf(bd.w * d));
                }
            }
        }
    }
    for (int base = 0; base < NS; base += 32) {
        const int idx = base + lane;
        bool ov = false;
        if (idx < NS) {
            const float c = Scol[rmain][idx];
            ov = (c >= fwx0) && (c <= fwxe);
        }
        unsigned m = __ballot_sync(0xffffffffu, ov);
        while (m) {
            const int kk = base + (__ffs(m) - 1); m &= m - 1;
            const int t  = (int)Scol[rmain][kk] - x0;
            if ((unsigned)t <= 1u) {
                const int j = Sj[rmain][kk];
                if (j > maxj[t]) { maxj[t] = j; blog[t] = Slh[rmain][kk]; }
                if (j >= 2*KB && j < 3*KB) cenm |= (1 << t);   // dyo == 0 band
            }
        }
    }

    // ---- per-pixel loss terms ----
    const float pv[2] = {cm2.x, cm2.y};
    float csum = 0.f, ssum = 0.f;
    #pragma unroll
    for (int i = 0; i < 2; i++) {
        const float p = fminf(fmaxf(pv[i], 1e-4f), 0.9999f);
        if (cenm & (1 << i)) {
            const float q = 1.0f - p;
            csum += q * q * (-__logf(p));                    // ALPHA=1, GAMMA=2
        } else if (posm & (1 << i)) {
            float q = 1.0f - gmax[i];
            float w = q * q; w = w * w;                      // BETA=4
            csum += w * p * p * (-__logf(1.0f - p));
        }
        if (maxj[i] >= 0) {
            const float d = fabsf(blog[i] - smap[(size_t)gq * 2 + i]);
            ssum += (d <= 1.0f) ? 0.5f * d * d : (d - 0.5f);
        }
    }

    // ---- block reduce (32 warps) ----
    #pragma unroll
    for (int off = 16; off; off >>= 1) {
        csum += __shfl_down_sync(0xffffffffu, csum, off);
        ssum += __shfl_down_sync(0xffffffffu, ssum, off);
    }
    if (lane == 0) { r_c[tid>>5] = csum; r_s[tid>>5] = ssum; }
    __syncthreads();
    if (tid < 32) {
        csum = r_c[tid]; ssum = r_s[tid];
        #pragma unroll
        for (int off = 16; off; off >>= 1) {
            csum += __shfl_down_sync(0xffffffffu, csum, off);
            ssum += __shfl_down_sync(0xffffffffu, ssum, off);
        }
    }
    if (tid == 0) {
        g_part[b] = make_float2(csum, ssum);
        __threadfence();
        unsigned old = atomicInc(&g_cnt, GRID - 1);   // wraps to 0 -> self-resetting
        s_last = (old == GRID - 1);
    }
    __syncthreads();

    // ---- last block finalizes (128 partials) ----
    if (s_last) {
        float c2 = 0.f, s2 = 0.f;
        if (tid < GRID) {
            volatile float* vp = (volatile float*)g_part;
            c2 = vp[tid * 2];
            s2 = vp[tid * 2 + 1];
        }
        #pragma unroll
        for (int off = 16; off; off >>= 1) {
            c2 += __shfl_down_sync(0xffffffffu, c2, off);
            s2 += __shfl_down_sync(0xffffffffu, s2, off);
        }
        if (lane == 0 && tid < GRID) { r_c[tid>>5] = c2; r_s[tid>>5] = s2; }
        __syncthreads();
        if (tid < 4) {
            c2 = r_c[tid]; s2 = r_s[tid];
            #pragma unroll
            for (int off = 2; off; off >>= 1) {
                c2 += __shfl_down_sync(0x0000000fu, c2, off);
                s2 += __shfl_down_sync(0x0000000fu, s2, off);
            }
            if (tid == 0) {
                out[0] = c2 * (1.0f / 64.0f);
                out[1] = s2 * (1.0f / 64.0f);
            }
        }
    }
}

extern "C" void kernel_launch(void* const* d_in, const int* in_sizes, int n_in,
                              void* d_out, int out_size) {
    const float* cm   = (const float*)d_in[0];
    const float* sm   = (const float*)d_in[1];
    const float* ann  = (const float*)d_in[2];
    const void*  strp = (n_in > 3) ? d_in[3] : nullptr;
    float* out = (float*)d_out;

    lz_fused_kernel<<<GRID, TPB>>>(cm, sm, ann, strp, out);
}